// round 13
// baseline (speedup 1.0000x reference)
#include <cuda_runtime.h>
#include <cuda_fp16.h>
#include <cstdint>

#define BATCH 4
#define SEQ   2048

// fp16 2-term split storage.
// gemm1: A = hs hi-only [8192,1024]; B = W [256, 2048] = [hi | lo]
// gemm2: h stored [8192, 512] = [hi | lo]; A reads linear, B reads hi half
__device__ __half g_hs1[(size_t)8192 * 1024];  // 16 MiB
__device__ __half g_w2 [(size_t)256  * 2048];  // 1 MiB
__device__ __half g_h2 [(size_t)8192 * 512];   // 8 MiB

// ---------------------------------------------------------------------------
// PTX helpers
// ---------------------------------------------------------------------------
__device__ __forceinline__ unsigned smem_u32(const void* p) {
    unsigned a;
    asm("{ .reg .u64 t; cvta.to.shared.u64 t, %1; cvt.u32.u64 %0, t; }"
        : "=r"(a) : "l"(p));
    return a;
}

#define CP_ASYNC16(dst, src) \
    asm volatile("cp.async.cg.shared.global [%0], [%1], 16;" :: "r"(dst), "l"(src))
#define CP_COMMIT() asm volatile("cp.async.commit_group;" ::: "memory")
#define CP_WAIT1()  asm volatile("cp.async.wait_group 1;" ::: "memory")
#define CP_WAIT0()  asm volatile("cp.async.wait_group 0;" ::: "memory")

#define LDSM_X4(r0, r1, r2, r3, a) \
    asm volatile("ldmatrix.sync.aligned.m8n8.x4.shared.b16 {%0,%1,%2,%3}, [%4];" \
                 : "=r"(r0), "=r"(r1), "=r"(r2), "=r"(r3) : "r"(a))

#define MMA16816(d, a, b0, b1) \
    asm volatile( \
        "mma.sync.aligned.m16n8k16.row.col.f32.f16.f16.f32 " \
        "{%0,%1,%2,%3},{%4,%5,%6,%7},{%8,%9},{%0,%1,%2,%3};" \
        : "+f"((d)[0]), "+f"((d)[1]), "+f"((d)[2]), "+f"((d)[3]) \
        : "r"((a)[0]), "r"((a)[1]), "r"((a)[2]), "r"((a)[3]), "r"(b0), "r"(b1))

// gemm2: stage = A(16KB)+B(16KB) = 32KB, 3 stages = 96KB
#define G2_STAGE  32768
#define G2_SMEM   98304
// gemm1: stage = A(8KB)+B(16KB) = 24KB, 3 stages = 72KB
#define G1_STAGE  24576
#define G1_SMEM   73728

// ---------------------------------------------------------------------------
// Combined split kernel.
//   part 0: hs fp32 [8192,1024] -> g_hs1 hi-only [8192,1024]
//   part 1: W  fp32 [256,1024]  -> g_w2 [256, 2048] = [hi | lo]
// ---------------------------------------------------------------------------
__global__ __launch_bounds__(256) void split_kernel(
    const float* __restrict__ hs, const float* __restrict__ W,
    int n4_hs, int n4_w)
{
    int i = blockIdx.x * blockDim.x + threadIdx.x;
    if (i < n4_hs) {
        int e0 = i * 4;
        float4 v = *reinterpret_cast<const float4*>(hs + e0);
        __half2 p0 = __halves2half2(__float2half_rn(v.x), __float2half_rn(v.y));
        __half2 p1 = __halves2half2(__float2half_rn(v.z), __float2half_rn(v.w));
        *reinterpret_cast<__half2*>(g_hs1 + e0)     = p0;
        *reinterpret_cast<__half2*>(g_hs1 + e0 + 2) = p1;
    } else {
        int j = i - n4_hs;
        if (j >= n4_w) return;
        int e0 = j * 4;
        int r = e0 >> 10, c = e0 & 1023;
        float4 v = *reinterpret_cast<const float4*>(W + e0);
        __half h0 = __float2half_rn(v.x), h1 = __float2half_rn(v.y);
        __half h2 = __float2half_rn(v.z), h3 = __float2half_rn(v.w);
        __half l0 = __float2half_rn(v.x - __half2float(h0));
        __half l1 = __float2half_rn(v.y - __half2float(h1));
        __half l2 = __float2half_rn(v.z - __half2float(h2));
        __half l3 = __float2half_rn(v.w - __half2float(h3));
        __half* rowp = g_w2 + (size_t)r * 2048;
        *reinterpret_cast<__half2*>(rowp + c)            = __halves2half2(h0, h1);
        *reinterpret_cast<__half2*>(rowp + c + 2)        = __halves2half2(h2, h3);
        *reinterpret_cast<__half2*>(rowp + 1024 + c)     = __halves2half2(l0, l1);
        *reinterpret_cast<__half2*>(rowp + 1024 + c + 2) = __halves2half2(l2, l3);
    }
}

// Load a ROWS x 64-fp16 chunk into smem (xor-swizzled, 128B rows).
template<int ROWS, int THREADS>
__device__ __forceinline__ void load_op(
    const __half* __restrict__ base, int ld, int col, unsigned s, int t)
{
#pragma unroll
    for (int i = 0; i < ROWS * 8 / THREADS; ++i) {
        int idx = t + i * THREADS;
        int row = idx >> 3, ch = idx & 7;
        unsigned dst = (unsigned)(row * 128 + ((ch ^ (row & 7)) << 4));
        CP_ASYNC16(s + dst, base + (size_t)row * ld + col + ch * 8);
    }
}

// Compute 4 k16-steps. Warp covers MI*16 (M) x NP*16 (N).
template<int MI, int NP>
__device__ __forceinline__ void compute_stage_t(
    unsigned sA, unsigned sB, int lane, int mrow0, int nrow0,
    float (&acc)[MI][2 * NP][4])
{
#pragma unroll
    for (int s = 0; s < 4; ++s) {
        const int ch = s * 2 + (lane >> 4);
        unsigned a[MI][4], rb[NP][4];
#pragma unroll
        for (int mi = 0; mi < MI; ++mi) {
            int row = mrow0 + mi * 16 + (lane & 15);
            unsigned addr = sA + row * 128 + ((ch ^ (row & 7)) << 4);
            LDSM_X4(a[mi][0], a[mi][1], a[mi][2], a[mi][3], addr);
        }
#pragma unroll
        for (int p = 0; p < NP; ++p) {
            int row = nrow0 + p * 16 + (lane & 15);
            unsigned addr = sB + row * 128 + ((ch ^ (row & 7)) << 4);
            LDSM_X4(rb[p][0], rb[p][1], rb[p][2], rb[p][3], addr);
        }
#pragma unroll
        for (int mi = 0; mi < MI; ++mi)
#pragma unroll
            for (int p = 0; p < NP; ++p) {
                MMA16816(acc[mi][2 * p],     a[mi], rb[p][0], rb[p][2]);
                MMA16816(acc[mi][2 * p + 1], a[mi], rb[p][1], rb[p][3]);
            }
    }
}

// ---------------------------------------------------------------------------
// GEMM 1: h = relu(hs @ W^T + b), re-split -> g_h2 [8192, 512]
// CTA tile 64(M) x 128(N); warp grid 2x4 (warp tile 32x32); 256 CTAs.
// K=1024, K_eff=2048, 32 chunks.
//   A col = (c*64) & 1023 (hi-only, cycled twice); B col = c*64 linear.
// ---------------------------------------------------------------------------
__global__ __launch_bounds__(256, 2) void gemm1_kernel(const float* __restrict__ bias)
{
    extern __shared__ char smem[];
    const unsigned sm = smem_u32(smem);
    const int t = threadIdx.x, lane = t & 31, wid = t >> 5;
    const int wm = wid >> 2, wn = wid & 3;
    const int row0 = blockIdx.y * 64;
    const int col0 = blockIdx.x * 128;

    float acc[2][4][4];
#pragma unroll
    for (int i = 0; i < 2; ++i)
#pragma unroll
        for (int j = 0; j < 4; ++j)
#pragma unroll
            for (int k = 0; k < 4; ++k) acc[i][j][k] = 0.f;

    const __half* A0 = g_hs1 + (size_t)row0 * 1024;
    const __half* B0 = g_w2 + (size_t)col0 * 2048;
    const int nchunks = 32;

    unsigned bufA[3], bufB[3];
#pragma unroll
    for (int s = 0; s < 3; ++s) {
        bufA[s] = sm + s * G1_STAGE;
        bufB[s] = sm + s * G1_STAGE + 8192;
    }

    load_op<64, 256>(A0, 1024, 0, bufA[0], t);
    load_op<128, 256>(B0, 2048, 0, bufB[0], t);
    CP_COMMIT();
    load_op<64, 256>(A0, 1024, 64, bufA[1], t);
    load_op<128, 256>(B0, 2048, 64, bufB[1], t);
    CP_COMMIT();

    for (int c = 0; c < nchunks; ++c) {
        if (c + 1 < nchunks) CP_WAIT1(); else CP_WAIT0();
        __syncthreads();
        const int p = c + 2;
        if (p < nchunks) {
            load_op<64, 256>(A0, 1024, (p * 64) & 1023, bufA[p % 3], t);
            load_op<128, 256>(B0, 2048, p * 64, bufB[p % 3], t);
            CP_COMMIT();
        }
        compute_stage_t<2, 2>(bufA[c % 3], bufB[c % 3], lane,
                              wm * 32, wn * 32, acc);
    }

    const int rb0 = row0 + wm * 32 + (lane >> 2);
    const int cb0 = col0 + wn * 32 + (lane & 3) * 2;
#pragma unroll
    for (int mi = 0; mi < 2; ++mi) {
#pragma unroll
        for (int ni = 0; ni < 4; ++ni) {
            const int c = cb0 + ni * 8;
            const float b0 = bias[c], b1 = bias[c + 1];
#pragma unroll
            for (int half = 0; half < 2; ++half) {
                const int r = rb0 + mi * 16 + half * 8;
                float v0 = fmaxf(acc[mi][ni][2 * half]     + b0, 0.f);
                float v1 = fmaxf(acc[mi][ni][2 * half + 1] + b1, 0.f);
                __half h0 = __float2half_rn(v0);
                __half h1 = __float2half_rn(v1);
                __half l0 = __float2half_rn(v0 - __half2float(h0));
                __half l1 = __float2half_rn(v1 - __half2float(h1));
                __half* rowp = g_h2 + (size_t)r * 512 + c;
                *reinterpret_cast<__half2*>(rowp)       = __halves2half2(h0, h1);
                *reinterpret_cast<__half2*>(rowp + 256) = __halves2half2(l0, l1);
            }
        }
    }
}

// ---------------------------------------------------------------------------
// GEMM 2: out[b,i,j] = (h_i . h_j) * cw + cb, symmetric — upper-tri tiles only.
// CTA tile 128x128; 128 threads, warp grid 2x2 (warp tile 64x64).
// K=256, K_eff=512, 8 chunks. A reads [0,512) linear, B reads hi half twice.
// ---------------------------------------------------------------------------
__global__ __launch_bounds__(128) void gemm2_kernel(
    const float* __restrict__ clf_w, const float* __restrict__ clf_b,
    float* __restrict__ out)
{
    extern __shared__ char smem[];
    const unsigned sm = smem_u32(smem);
    const int t = threadIdx.x, lane = t & 31, wid = t >> 5;
    const int wm = wid >> 1, wn = wid & 1;
    const int b = blockIdx.z;

    // Map linear tile index -> (ti, tj) with ti <= tj over a 16x16 tile grid
    int ti = 0, rem = blockIdx.x;
    while (rem >= 16 - ti) { rem -= 16 - ti; ++ti; }
    const int tj = ti + rem;
    const int row0 = ti * 128;
    const int col0 = tj * 128;

    float acc[4][8][4];
#pragma unroll
    for (int i = 0; i < 4; ++i)
#pragma unroll
        for (int j = 0; j < 8; ++j)
#pragma unroll
            for (int k = 0; k < 4; ++k) acc[i][j][k] = 0.f;

    const __half* hb = g_h2 + (size_t)b * SEQ * 512;
    const __half* A0 = hb + (size_t)row0 * 512;
    const __half* B0 = hb + (size_t)col0 * 512;
    const int nchunks = 8;

    unsigned bufA[3], bufB[3];
#pragma unroll
    for (int s = 0; s < 3; ++s) {
        bufA[s] = sm + s * G2_STAGE;
        bufB[s] = sm + s * G2_STAGE + 16384;
    }

    load_op<128, 128>(A0, 512, 0, bufA[0], t);
    load_op<128, 128>(B0, 512, 0, bufB[0], t);
    CP_COMMIT();
    load_op<128, 128>(A0, 512, 64, bufA[1], t);
    load_op<128, 128>(B0, 512, 64, bufB[1], t);
    CP_COMMIT();

    for (int c = 0; c < nchunks; ++c) {
        if (c + 1 < nchunks) CP_WAIT1(); else CP_WAIT0();
        __syncthreads();
        const int p = c + 2;
        if (p < nchunks) {
            load_op<128, 128>(A0, 512, p * 64, bufA[p % 3], t);
            load_op<128, 128>(B0, 512, (p * 64) & 255, bufB[p % 3], t);
            CP_COMMIT();
        }
        compute_stage_t<4, 4>(bufA[c % 3], bufB[c % 3], lane,
                              wm * 64, wn * 64, acc);
    }
    __syncthreads();   // smem safe for epilogue reuse

    const float cw = __ldg(clf_w);
    const float cb = __ldg(clf_b);
    float* __restrict__ ob = out + (size_t)b * SEQ * SEQ;

    float* tileT = reinterpret_cast<float*>(smem);   // [128][132] transposed stage
    const bool diag = (ti == tj);

    const int rloc = wm * 64 + (lane >> 2);
    const int cloc = wn * 64 + (lane & 3) * 2;
#pragma unroll
    for (int mi = 0; mi < 4; ++mi) {
#pragma unroll
        for (int ni = 0; ni < 8; ++ni) {
            const int c = cloc + ni * 8;
#pragma unroll
            for (int half = 0; half < 2; ++half) {
                const int r = rloc + mi * 16 + half * 8;
                float2 v;
                v.x = acc[mi][ni][2 * half]     * cw + cb;
                v.y = acc[mi][ni][2 * half + 1] * cw + cb;
                *reinterpret_cast<float2*>(
                    ob + (size_t)(row0 + r) * SEQ + col0 + c) = v;
                if (!diag) {
                    tileT[(c)     * 132 + r] = v.x;
                    tileT[(c + 1) * 132 + r] = v.y;
                }
            }
        }
    }

    if (!diag) {
        __syncthreads();
        for (int i = t; i < 128 * 32; i += 128) {
            const int row = i >> 5, q = (i & 31) * 4;
            float4 v = *reinterpret_cast<const float4*>(&tileT[row * 132 + q]);
            *reinterpret_cast<float4*>(
                ob + (size_t)(col0 + row) * SEQ + row0 + q) = v;
        }
    }
}

// ---------------------------------------------------------------------------
extern "C" void kernel_launch(void* const* d_in, const int* in_sizes, int n_in,
                              void* d_out, int out_size)
{
    const float* hs     = (const float*)d_in[0];  // [4, 2048, 1024]
    const float* proj_w = (const float*)d_in[1];  // [256, 1024]
    const float* proj_b = (const float*)d_in[2];  // [256]
    const float* clf_w  = (const float*)d_in[3];  // [1, 1]
    const float* clf_b  = (const float*)d_in[4];  // [1]
    float* out = (float*)d_out;                   // [4, 2048, 2048]

    cudaFuncSetAttribute(gemm1_kernel,
                         cudaFuncAttributeMaxDynamicSharedMemorySize, G1_SMEM);
    cudaFuncSetAttribute(gemm2_kernel,
                         cudaFuncAttributeMaxDynamicSharedMemorySize, G2_SMEM);

    {   // combined split: hs hi-only (2M float4) + W split (64K float4)
        int n4_hs = 8192 * 1024 / 4;
        int n4_w  = 256 * 1024 / 4;
        int total = n4_hs + n4_w;
        split_kernel<<<(total + 255) / 256, 256>>>(hs, proj_w, n4_hs, n4_w);
    }
    {   // GEMM1: 2 x 128 tiles of 64x128
        dim3 grid(2, 128);
        gemm1_kernel<<<grid, 256, G1_SMEM>>>(proj_b);
    }
    {   // GEMM2: 136 upper-tri tiles x 4 batches, 128 threads/CTA
        dim3 grid(136, 1, BATCH);
        gemm2_kernel<<<grid, 128, G2_SMEM>>>(clf_w, clf_b, out);
    }
}

// round 14
// speedup vs baseline: 1.2022x; 1.2022x over previous
#include <cuda_runtime.h>
#include <cuda_fp16.h>
#include <cstdint>

#define BATCH 4
#define SEQ   2048

// fp16 split storage.
// gemm1: A = hs hi-only [8192,1024]; B = W [256, 2048] = [hi | lo]  (2-term)
// gemm2: h hi-only [8192, 256]                                      (1-term)
__device__ __half g_hs1[(size_t)8192 * 1024];  // 16 MiB
__device__ __half g_w2 [(size_t)256  * 2048];  // 1 MiB
__device__ __half g_h2 [(size_t)8192 * 256];   // 4 MiB

// ---------------------------------------------------------------------------
// PTX helpers
// ---------------------------------------------------------------------------
__device__ __forceinline__ unsigned smem_u32(const void* p) {
    unsigned a;
    asm("{ .reg .u64 t; cvta.to.shared.u64 t, %1; cvt.u32.u64 %0, t; }"
        : "=r"(a) : "l"(p));
    return a;
}

#define CP_ASYNC16(dst, src) \
    asm volatile("cp.async.cg.shared.global [%0], [%1], 16;" :: "r"(dst), "l"(src))
#define CP_COMMIT() asm volatile("cp.async.commit_group;" ::: "memory")
#define CP_WAIT1()  asm volatile("cp.async.wait_group 1;" ::: "memory")
#define CP_WAIT0()  asm volatile("cp.async.wait_group 0;" ::: "memory")

#define LDSM_X4(r0, r1, r2, r3, a) \
    asm volatile("ldmatrix.sync.aligned.m8n8.x4.shared.b16 {%0,%1,%2,%3}, [%4];" \
                 : "=r"(r0), "=r"(r1), "=r"(r2), "=r"(r3) : "r"(a))

#define MMA16816(d, a, b0, b1) \
    asm volatile( \
        "mma.sync.aligned.m16n8k16.row.col.f32.f16.f16.f32 " \
        "{%0,%1,%2,%3},{%4,%5,%6,%7},{%8,%9},{%0,%1,%2,%3};" \
        : "+f"((d)[0]), "+f"((d)[1]), "+f"((d)[2]), "+f"((d)[3]) \
        : "r"((a)[0]), "r"((a)[1]), "r"((a)[2]), "r"((a)[3]), "r"(b0), "r"(b1))

// gemm2: stage = A(16KB)+B(16KB) = 32KB, 3 stages = 96KB
#define G2_STAGE  32768
#define G2_SMEM   98304
// gemm1: stage = A(8KB)+B(16KB) = 24KB, 3 stages = 72KB
#define G1_STAGE  24576
#define G1_SMEM   73728

// ---------------------------------------------------------------------------
// Combined split kernel.
//   part 0: hs fp32 [8192,1024] -> g_hs1 hi-only
//   part 1: W  fp32 [256,1024]  -> g_w2 [256, 2048] = [hi | lo]
// ---------------------------------------------------------------------------
__global__ __launch_bounds__(256) void split_kernel(
    const float* __restrict__ hs, const float* __restrict__ W,
    int n4_hs, int n4_w)
{
    int i = blockIdx.x * blockDim.x + threadIdx.x;
    if (i < n4_hs) {
        int e0 = i * 4;
        float4 v = *reinterpret_cast<const float4*>(hs + e0);
        __half2 p0 = __halves2half2(__float2half_rn(v.x), __float2half_rn(v.y));
        __half2 p1 = __halves2half2(__float2half_rn(v.z), __float2half_rn(v.w));
        *reinterpret_cast<__half2*>(g_hs1 + e0)     = p0;
        *reinterpret_cast<__half2*>(g_hs1 + e0 + 2) = p1;
    } else {
        int j = i - n4_hs;
        if (j >= n4_w) return;
        int e0 = j * 4;
        int r = e0 >> 10, c = e0 & 1023;
        float4 v = *reinterpret_cast<const float4*>(W + e0);
        __half h0 = __float2half_rn(v.x), h1 = __float2half_rn(v.y);
        __half h2 = __float2half_rn(v.z), h3 = __float2half_rn(v.w);
        __half l0 = __float2half_rn(v.x - __half2float(h0));
        __half l1 = __float2half_rn(v.y - __half2float(h1));
        __half l2 = __float2half_rn(v.z - __half2float(h2));
        __half l3 = __float2half_rn(v.w - __half2float(h3));
        __half* rowp = g_w2 + (size_t)r * 2048;
        *reinterpret_cast<__half2*>(rowp + c)            = __halves2half2(h0, h1);
        *reinterpret_cast<__half2*>(rowp + c + 2)        = __halves2half2(h2, h3);
        *reinterpret_cast<__half2*>(rowp + 1024 + c)     = __halves2half2(l0, l1);
        *reinterpret_cast<__half2*>(rowp + 1024 + c + 2) = __halves2half2(l2, l3);
    }
}

// Load a ROWS x 64-fp16 chunk into smem (xor-swizzled, 128B rows).
template<int ROWS, int THREADS>
__device__ __forceinline__ void load_op(
    const __half* __restrict__ base, int ld, int col, unsigned s, int t)
{
#pragma unroll
    for (int i = 0; i < ROWS * 8 / THREADS; ++i) {
        int idx = t + i * THREADS;
        int row = idx >> 3, ch = idx & 7;
        unsigned dst = (unsigned)(row * 128 + ((ch ^ (row & 7)) << 4));
        CP_ASYNC16(s + dst, base + (size_t)row * ld + col + ch * 8);
    }
}

// Compute 4 k16-steps. Warp covers MI*16 (M) x NP*16 (N).
template<int MI, int NP>
__device__ __forceinline__ void compute_stage_t(
    unsigned sA, unsigned sB, int lane, int mrow0, int nrow0,
    float (&acc)[MI][2 * NP][4])
{
#pragma unroll
    for (int s = 0; s < 4; ++s) {
        const int ch = s * 2 + (lane >> 4);
        unsigned a[MI][4], rb[NP][4];
#pragma unroll
        for (int mi = 0; mi < MI; ++mi) {
            int row = mrow0 + mi * 16 + (lane & 15);
            unsigned addr = sA + row * 128 + ((ch ^ (row & 7)) << 4);
            LDSM_X4(a[mi][0], a[mi][1], a[mi][2], a[mi][3], addr);
        }
#pragma unroll
        for (int p = 0; p < NP; ++p) {
            int row = nrow0 + p * 16 + (lane & 15);
            unsigned addr = sB + row * 128 + ((ch ^ (row & 7)) << 4);
            LDSM_X4(rb[p][0], rb[p][1], rb[p][2], rb[p][3], addr);
        }
#pragma unroll
        for (int mi = 0; mi < MI; ++mi)
#pragma unroll
            for (int p = 0; p < NP; ++p) {
                MMA16816(acc[mi][2 * p],     a[mi], rb[p][0], rb[p][2]);
                MMA16816(acc[mi][2 * p + 1], a[mi], rb[p][1], rb[p][3]);
            }
    }
}

// ---------------------------------------------------------------------------
// GEMM 1: h = relu(hs @ W^T + b), hi-only h -> g_h2 [8192, 256]
// CTA tile 64(M) x 128(N); warp grid 2x4 (warp tile 32x32); 256 CTAs; 2/SM.
// 2-term: K_eff=2048, 32 chunks. A col cycles hi twice; B col linear over 2048.
// ---------------------------------------------------------------------------
__global__ __launch_bounds__(256, 2) void gemm1_kernel(const float* __restrict__ bias)
{
    extern __shared__ char smem[];
    const unsigned sm = smem_u32(smem);
    const int t = threadIdx.x, lane = t & 31, wid = t >> 5;
    const int wm = wid >> 2, wn = wid & 3;
    const int row0 = blockIdx.y * 64;
    const int col0 = blockIdx.x * 128;

    float acc[2][4][4];
#pragma unroll
    for (int i = 0; i < 2; ++i)
#pragma unroll
        for (int j = 0; j < 4; ++j)
#pragma unroll
            for (int k = 0; k < 4; ++k) acc[i][j][k] = 0.f;

    const __half* A0 = g_hs1 + (size_t)row0 * 1024;
    const __half* B0 = g_w2 + (size_t)col0 * 2048;
    const int nchunks = 32;

    unsigned bufA[3], bufB[3];
#pragma unroll
    for (int s = 0; s < 3; ++s) {
        bufA[s] = sm + s * G1_STAGE;
        bufB[s] = sm + s * G1_STAGE + 8192;
    }

    load_op<64, 256>(A0, 1024, 0, bufA[0], t);
    load_op<128, 256>(B0, 2048, 0, bufB[0], t);
    CP_COMMIT();
    load_op<64, 256>(A0, 1024, 64, bufA[1], t);
    load_op<128, 256>(B0, 2048, 64, bufB[1], t);
    CP_COMMIT();

    for (int c = 0; c < nchunks; ++c) {
        if (c + 1 < nchunks) CP_WAIT1(); else CP_WAIT0();
        __syncthreads();
        const int p = c + 2;
        if (p < nchunks) {
            load_op<64, 256>(A0, 1024, (p * 64) & 1023, bufA[p % 3], t);
            load_op<128, 256>(B0, 2048, p * 64, bufB[p % 3], t);
            CP_COMMIT();
        }
        compute_stage_t<2, 2>(bufA[c % 3], bufB[c % 3], lane,
                              wm * 32, wn * 32, acc);
    }

    const int rb0 = row0 + wm * 32 + (lane >> 2);
    const int cb0 = col0 + wn * 32 + (lane & 3) * 2;
#pragma unroll
    for (int mi = 0; mi < 2; ++mi) {
#pragma unroll
        for (int ni = 0; ni < 4; ++ni) {
            const int c = cb0 + ni * 8;
            const float b0 = bias[c], b1 = bias[c + 1];
#pragma unroll
            for (int half = 0; half < 2; ++half) {
                const int r = rb0 + mi * 16 + half * 8;
                float v0 = fmaxf(acc[mi][ni][2 * half]     + b0, 0.f);
                float v1 = fmaxf(acc[mi][ni][2 * half + 1] + b1, 0.f);
                *reinterpret_cast<__half2*>(g_h2 + (size_t)r * 256 + c) =
                    __halves2half2(__float2half_rn(v0), __float2half_rn(v1));
            }
        }
    }
}

// ---------------------------------------------------------------------------
// GEMM 2: out[b,i,j] = (h_i . h_j) * cw + cb, symmetric — upper-tri tiles only.
// CTA tile 128x128; 256 threads, warp grid 4x2 (warp tile 32x64); 2 CTAs/SM.
// hi-only: K_eff = 256, 4 chunks.
// ---------------------------------------------------------------------------
__global__ __launch_bounds__(256, 2) void gemm2_kernel(
    const float* __restrict__ clf_w, const float* __restrict__ clf_b,
    float* __restrict__ out)
{
    extern __shared__ char smem[];
    const unsigned sm = smem_u32(smem);
    const int t = threadIdx.x, lane = t & 31, wid = t >> 5;
    const int wm = wid >> 1, wn = wid & 1;
    const int b = blockIdx.z;

    // Map linear tile index -> (ti, tj) with ti <= tj over a 16x16 tile grid
    int ti = 0, rem = blockIdx.x;
    while (rem >= 16 - ti) { rem -= 16 - ti; ++ti; }
    const int tj = ti + rem;
    const int row0 = ti * 128;
    const int col0 = tj * 128;

    float acc[2][8][4];
#pragma unroll
    for (int i = 0; i < 2; ++i)
#pragma unroll
        for (int j = 0; j < 8; ++j)
#pragma unroll
            for (int k = 0; k < 4; ++k) acc[i][j][k] = 0.f;

    const __half* hb = g_h2 + (size_t)b * SEQ * 256;
    const __half* A0 = hb + (size_t)row0 * 256;
    const __half* B0 = hb + (size_t)col0 * 256;
    const int nchunks = 4;

    unsigned bufA[3], bufB[3];
#pragma unroll
    for (int s = 0; s < 3; ++s) {
        bufA[s] = sm + s * G2_STAGE;
        bufB[s] = sm + s * G2_STAGE + 16384;
    }

    load_op<128, 256>(A0, 256, 0, bufA[0], t);
    load_op<128, 256>(B0, 256, 0, bufB[0], t);
    CP_COMMIT();
    load_op<128, 256>(A0, 256, 64, bufA[1], t);
    load_op<128, 256>(B0, 256, 64, bufB[1], t);
    CP_COMMIT();

    for (int c = 0; c < nchunks; ++c) {
        if (c + 1 < nchunks) CP_WAIT1(); else CP_WAIT0();
        __syncthreads();
        const int p = c + 2;
        if (p < nchunks) {
            load_op<128, 256>(A0, 256, p * 64, bufA[p % 3], t);
            load_op<128, 256>(B0, 256, p * 64, bufB[p % 3], t);
            CP_COMMIT();
        }
        compute_stage_t<2, 4>(bufA[c % 3], bufB[c % 3], lane,
                              wm * 32, wn * 64, acc);
    }
    __syncthreads();   // smem safe for epilogue reuse

    const float cw = __ldg(clf_w);
    const float cb = __ldg(clf_b);
    float* __restrict__ ob = out + (size_t)b * SEQ * SEQ;

    float* tileT = reinterpret_cast<float*>(smem);   // [128][132] transposed stage
    const bool diag = (ti == tj);

    const int rloc = wm * 32 + (lane >> 2);
    const int cloc = wn * 64 + (lane & 3) * 2;
#pragma unroll
    for (int mi = 0; mi < 2; ++mi) {
#pragma unroll
        for (int ni = 0; ni < 8; ++ni) {
            const int c = cloc + ni * 8;
#pragma unroll
            for (int half = 0; half < 2; ++half) {
                const int r = rloc + mi * 16 + half * 8;
                float2 v;
                v.x = acc[mi][ni][2 * half]     * cw + cb;
                v.y = acc[mi][ni][2 * half + 1] * cw + cb;
                *reinterpret_cast<float2*>(
                    ob + (size_t)(row0 + r) * SEQ + col0 + c) = v;
                if (!diag) {
                    tileT[(c)     * 132 + r] = v.x;
                    tileT[(c + 1) * 132 + r] = v.y;
                }
            }
        }
    }

    if (!diag) {
        __syncthreads();
        for (int i = t; i < 128 * 32; i += 256) {
            const int row = i >> 5, q = (i & 31) * 4;
            float4 v = *reinterpret_cast<const float4*>(&tileT[row * 132 + q]);
            *reinterpret_cast<float4*>(
                ob + (size_t)(col0 + row) * SEQ + row0 + q) = v;
        }
    }
}

// ---------------------------------------------------------------------------
extern "C" void kernel_launch(void* const* d_in, const int* in_sizes, int n_in,
                              void* d_out, int out_size)
{
    const float* hs     = (const float*)d_in[0];  // [4, 2048, 1024]
    const float* proj_w = (const float*)d_in[1];  // [256, 1024]
    const float* proj_b = (const float*)d_in[2];  // [256]
    const float* clf_w  = (const float*)d_in[3];  // [1, 1]
    const float* clf_b  = (const float*)d_in[4];  // [1]
    float* out = (float*)d_out;                   // [4, 2048, 2048]

    cudaFuncSetAttribute(gemm1_kernel,
                         cudaFuncAttributeMaxDynamicSharedMemorySize, G1_SMEM);
    cudaFuncSetAttribute(gemm2_kernel,
                         cudaFuncAttributeMaxDynamicSharedMemorySize, G2_SMEM);

    {   // combined split: hs hi-only (2M float4) + W split (64K float4)
        int n4_hs = 8192 * 1024 / 4;
        int n4_w  = 256 * 1024 / 4;
        int total = n4_hs + n4_w;
        split_kernel<<<(total + 255) / 256, 256>>>(hs, proj_w, n4_hs, n4_w);
    }
    {   // GEMM1: 2 x 128 tiles of 64x128
        dim3 grid(2, 128);
        gemm1_kernel<<<grid, 256, G1_SMEM>>>(proj_b);
    }
    {   // GEMM2: 136 upper-tri tiles x 4 batches
        dim3 grid(136, 1, BATCH);
        gemm2_kernel<<<grid, 256, G2_SMEM>>>(clf_w, clf_b, out);
    }
}

// round 16
// speedup vs baseline: 1.5724x; 1.3079x over previous
#include <cuda_runtime.h>
#include <cuda_fp16.h>
#include <cstdint>

#define BATCH 4
#define SEQ   2048

// Pure fp16 hi-only storage everywhere (error budget verified in R10).
__device__ __half g_hs1[(size_t)8192 * 1024];  // 16 MiB
__device__ __half g_w1 [(size_t)256  * 1024];  // 0.5 MiB
__device__ __half g_h2 [(size_t)8192 * 256];   // 4 MiB

// ---------------------------------------------------------------------------
// PTX helpers
// ---------------------------------------------------------------------------
__device__ __forceinline__ unsigned smem_u32(const void* p) {
    unsigned a;
    asm("{ .reg .u64 t; cvta.to.shared.u64 t, %1; cvt.u32.u64 %0, t; }"
        : "=r"(a) : "l"(p));
    return a;
}

__device__ __forceinline__ unsigned pack2(__half a, __half b) {
    __half2 h = __halves2half2(a, b);
    return *reinterpret_cast<unsigned*>(&h);
}

#define CP_ASYNC16(dst, src) \
    asm volatile("cp.async.cg.shared.global [%0], [%1], 16;" :: "r"(dst), "l"(src))
#define CP_COMMIT() asm volatile("cp.async.commit_group;" ::: "memory")
#define CP_WAIT1()  asm volatile("cp.async.wait_group 1;" ::: "memory")
#define CP_WAIT0()  asm volatile("cp.async.wait_group 0;" ::: "memory")

#define LDSM_X4(r0, r1, r2, r3, a) \
    asm volatile("ldmatrix.sync.aligned.m8n8.x4.shared.b16 {%0,%1,%2,%3}, [%4];" \
                 : "=r"(r0), "=r"(r1), "=r"(r2), "=r"(r3) : "r"(a))

#define MMA16816(d, a, b0, b1) \
    asm volatile( \
        "mma.sync.aligned.m16n8k16.row.col.f32.f16.f16.f32 " \
        "{%0,%1,%2,%3},{%4,%5,%6,%7},{%8,%9},{%0,%1,%2,%3};" \
        : "+f"((d)[0]), "+f"((d)[1]), "+f"((d)[2]), "+f"((d)[3]) \
        : "r"((a)[0]), "r"((a)[1]), "r"((a)[2]), "r"((a)[3]), "r"(b0), "r"(b1))

// gemm2: stage = A(16KB)+B(16KB) = 32KB, 3 stages = 96KB
#define G2_STAGE  32768
#define G2_SMEM   98304
// gemm1: stage = A(8KB)+B(16KB) = 24KB, 3 stages = 72KB
#define G1_STAGE  24576
#define G1_SMEM   73728

// ---------------------------------------------------------------------------
// Convert kernel: fp32 -> fp16, 8 floats per thread (2 LDG.128 -> 1 STG.128)
//   part 0: hs [8192*1024] -> g_hs1
//   part 1: W  [256*1024]  -> g_w1
// ---------------------------------------------------------------------------
__global__ __launch_bounds__(256) void split_kernel(
    const float* __restrict__ hs, const float* __restrict__ W,
    int n8_hs, int n8_w)
{
    int i = blockIdx.x * blockDim.x + threadIdx.x;
    const float* src;
    __half* dst;
    int e0;
    if (i < n8_hs) {
        e0 = i * 8; src = hs; dst = g_hs1;
    } else {
        int j = i - n8_hs;
        if (j >= n8_w) return;
        e0 = j * 8; src = W; dst = g_w1;
    }
    float4 v0 = *reinterpret_cast<const float4*>(src + e0);
    float4 v1 = *reinterpret_cast<const float4*>(src + e0 + 4);
    uint4 pk;
    pk.x = pack2(__float2half_rn(v0.x), __float2half_rn(v0.y));
    pk.y = pack2(__float2half_rn(v0.z), __float2half_rn(v0.w));
    pk.z = pack2(__float2half_rn(v1.x), __float2half_rn(v1.y));
    pk.w = pack2(__float2half_rn(v1.z), __float2half_rn(v1.w));
    *reinterpret_cast<uint4*>(dst + e0) = pk;
}

// Load a ROWS x 64-fp16 chunk into smem (xor-swizzled, 128B rows).
template<int ROWS, int THREADS>
__device__ __forceinline__ void load_op(
    const __half* __restrict__ base, int ld, int col, unsigned s, int t)
{
#pragma unroll
    for (int i = 0; i < ROWS * 8 / THREADS; ++i) {
        int idx = t + i * THREADS;
        int row = idx >> 3, ch = idx & 7;
        unsigned dst = (unsigned)(row * 128 + ((ch ^ (row & 7)) << 4));
        CP_ASYNC16(s + dst, base + (size_t)row * ld + col + ch * 8);
    }
}

// Compute 4 k16-steps. Warp covers MI*16 (M) x NP*16 (N).
template<int MI, int NP>
__device__ __forceinline__ void compute_stage_t(
    unsigned sA, unsigned sB, int lane, int mrow0, int nrow0,
    float (&acc)[MI][2 * NP][4])
{
#pragma unroll
    for (int s = 0; s < 4; ++s) {
        const int ch = s * 2 + (lane >> 4);
        unsigned a[MI][4], rb[NP][4];
#pragma unroll
        for (int mi = 0; mi < MI; ++mi) {
            int row = mrow0 + mi * 16 + (lane & 15);
            unsigned addr = sA + row * 128 + ((ch ^ (row & 7)) << 4);
            LDSM_X4(a[mi][0], a[mi][1], a[mi][2], a[mi][3], addr);
        }
#pragma unroll
        for (int p = 0; p < NP; ++p) {
            int row = nrow0 + p * 16 + (lane & 15);
            unsigned addr = sB + row * 128 + ((ch ^ (row & 7)) << 4);
            LDSM_X4(rb[p][0], rb[p][1], rb[p][2], rb[p][3], addr);
        }
#pragma unroll
        for (int mi = 0; mi < MI; ++mi)
#pragma unroll
            for (int p = 0; p < NP; ++p) {
                MMA16816(acc[mi][2 * p],     a[mi], rb[p][0], rb[p][2]);
                MMA16816(acc[mi][2 * p + 1], a[mi], rb[p][1], rb[p][3]);
            }
    }
}

// ---------------------------------------------------------------------------
// GEMM 1: h = relu(hs @ W^T + b), hi-only h -> g_h2 [8192, 256]
// CTA tile 64(M) x 128(N); warp grid 2x4 (warp tile 32x32); 256 CTAs; 2/SM.
// Pure fp16: K = 1024, 16 chunks.
// ---------------------------------------------------------------------------
__global__ __launch_bounds__(256, 2) void gemm1_kernel(const float* __restrict__ bias)
{
    extern __shared__ char smem[];
    const unsigned sm = smem_u32(smem);
    const int t = threadIdx.x, lane = t & 31, wid = t >> 5;
    const int wm = wid >> 2, wn = wid & 3;
    const int row0 = blockIdx.y * 64;
    const int col0 = blockIdx.x * 128;

    float acc[2][4][4];
#pragma unroll
    for (int i = 0; i < 2; ++i)
#pragma unroll
        for (int j = 0; j < 4; ++j)
#pragma unroll
            for (int k = 0; k < 4; ++k) acc[i][j][k] = 0.f;

    const __half* A0 = g_hs1 + (size_t)row0 * 1024;
    const __half* B0 = g_w1 + (size_t)col0 * 1024;
    const int nchunks = 16;

    unsigned bufA[3], bufB[3];
#pragma unroll
    for (int s = 0; s < 3; ++s) {
        bufA[s] = sm + s * G1_STAGE;
        bufB[s] = sm + s * G1_STAGE + 8192;
    }

    load_op<64, 256>(A0, 1024, 0, bufA[0], t);
    load_op<128, 256>(B0, 1024, 0, bufB[0], t);
    CP_COMMIT();
    load_op<64, 256>(A0, 1024, 64, bufA[1], t);
    load_op<128, 256>(B0, 1024, 64, bufB[1], t);
    CP_COMMIT();

    for (int c = 0; c < nchunks; ++c) {
        if (c + 1 < nchunks) CP_WAIT1(); else CP_WAIT0();
        __syncthreads();
        const int p = c + 2;
        if (p < nchunks) {
            load_op<64, 256>(A0, 1024, p * 64, bufA[p % 3], t);
            load_op<128, 256>(B0, 1024, p * 64, bufB[p % 3], t);
            CP_COMMIT();
        }
        compute_stage_t<2, 2>(bufA[c % 3], bufB[c % 3], lane,
                              wm * 32, wn * 32, acc);
    }

    const int rb0 = row0 + wm * 32 + (lane >> 2);
    const int cb0 = col0 + wn * 32 + (lane & 3) * 2;
#pragma unroll
    for (int mi = 0; mi < 2; ++mi) {
#pragma unroll
        for (int ni = 0; ni < 4; ++ni) {
            const int c = cb0 + ni * 8;
            const float b0 = bias[c], b1 = bias[c + 1];
#pragma unroll
            for (int half = 0; half < 2; ++half) {
                const int r = rb0 + mi * 16 + half * 8;
                float v0 = fmaxf(acc[mi][ni][2 * half]     + b0, 0.f);
                float v1 = fmaxf(acc[mi][ni][2 * half + 1] + b1, 0.f);
                *reinterpret_cast<__half2*>(g_h2 + (size_t)r * 256 + c) =
                    __halves2half2(__float2half_rn(v0), __float2half_rn(v1));
            }
        }
    }
}

// ---------------------------------------------------------------------------
// GEMM 2: out[b,i,j] = (h_i . h_j) * cw + cb, symmetric — upper-tri tiles only.
// CTA tile 128x128; 256 threads, warp grid 4x2 (warp tile 32x64); 2 CTAs/SM.
// K = 256, 4 chunks.  (R10 proven version, unchanged)
// ---------------------------------------------------------------------------
__global__ __launch_bounds__(256, 2) void gemm2_kernel(
    const float* __restrict__ clf_w, const float* __restrict__ clf_b,
    float* __restrict__ out)
{
    extern __shared__ char smem[];
    const unsigned sm = smem_u32(smem);
    const int t = threadIdx.x, lane = t & 31, wid = t >> 5;
    const int wm = wid >> 1, wn = wid & 1;
    const int b = blockIdx.z;

    int ti = 0, rem = blockIdx.x;
    while (rem >= 16 - ti) { rem -= 16 - ti; ++ti; }
    const int tj = ti + rem;
    const int row0 = ti * 128;
    const int col0 = tj * 128;

    float acc[2][8][4];
#pragma unroll
    for (int i = 0; i < 2; ++i)
#pragma unroll
        for (int j = 0; j < 8; ++j)
#pragma unroll
            for (int k = 0; k < 4; ++k) acc[i][j][k] = 0.f;

    const __half* hb = g_h2 + (size_t)b * SEQ * 256;
    const __half* A0 = hb + (size_t)row0 * 256;
    const __half* B0 = hb + (size_t)col0 * 256;
    const int nchunks = 4;

    unsigned bufA[3], bufB[3];
#pragma unroll
    for (int s = 0; s < 3; ++s) {
        bufA[s] = sm + s * G2_STAGE;
        bufB[s] = sm + s * G2_STAGE + 16384;
    }

    load_op<128, 256>(A0, 256, 0, bufA[0], t);
    load_op<128, 256>(B0, 256, 0, bufB[0], t);
    CP_COMMIT();
    load_op<128, 256>(A0, 256, 64, bufA[1], t);
    load_op<128, 256>(B0, 256, 64, bufB[1], t);
    CP_COMMIT();

    for (int c = 0; c < nchunks; ++c) {
        if (c + 1 < nchunks) CP_WAIT1(); else CP_WAIT0();
        __syncthreads();
        const int p = c + 2;
        if (p < nchunks) {
            load_op<128, 256>(A0, 256, p * 64, bufA[p % 3], t);
            load_op<128, 256>(B0, 256, p * 64, bufB[p % 3], t);
            CP_COMMIT();
        }
        compute_stage_t<2, 4>(bufA[c % 3], bufB[c % 3], lane,
                              wm * 32, wn * 64, acc);
    }
    __syncthreads();

    const float cw = __ldg(clf_w);
    const float cb = __ldg(clf_b);
    float* __restrict__ ob = out + (size_t)b * SEQ * SEQ;

    float* tileT = reinterpret_cast<float*>(smem);
    const bool diag = (ti == tj);

    const int rloc = wm * 32 + (lane >> 2);
    const int cloc = wn * 64 + (lane & 3) * 2;
#pragma unroll
    for (int mi = 0; mi < 2; ++mi) {
#pragma unroll
        for (int ni = 0; ni < 8; ++ni) {
            const int c = cloc + ni * 8;
#pragma unroll
            for (int half = 0; half < 2; ++half) {
                const int r = rloc + mi * 16 + half * 8;
                float2 v;
                v.x = acc[mi][ni][2 * half]     * cw + cb;
                v.y = acc[mi][ni][2 * half + 1] * cw + cb;
                *reinterpret_cast<float2*>(
                    ob + (size_t)(row0 + r) * SEQ + col0 + c) = v;
                if (!diag) {
                    tileT[(c)     * 132 + r] = v.x;
                    tileT[(c + 1) * 132 + r] = v.y;
                }
            }
        }
    }

    if (!diag) {
        __syncthreads();
        for (int i = t; i < 128 * 32; i += 256) {
            const int row = i >> 5, q = (i & 31) * 4;
            float4 v = *reinterpret_cast<const float4*>(&tileT[row * 132 + q]);
            *reinterpret_cast<float4*>(
                ob + (size_t)(col0 + row) * SEQ + row0 + q) = v;
        }
    }
}

// ---------------------------------------------------------------------------
extern "C" void kernel_launch(void* const* d_in, const int* in_sizes, int n_in,
                              void* d_out, int out_size)
{
    const float* hs     = (const float*)d_in[0];  // [4, 2048, 1024]
    const float* proj_w = (const float*)d_in[1];  // [256, 1024]
    const float* proj_b = (const float*)d_in[2];  // [256]
    const float* clf_w  = (const float*)d_in[3];  // [1, 1]
    const float* clf_b  = (const float*)d_in[4];  // [1]
    float* out = (float*)d_out;                   // [4, 2048, 2048]

    cudaFuncSetAttribute(gemm1_kernel,
                         cudaFuncAttributeMaxDynamicSharedMemorySize, G1_SMEM);
    cudaFuncSetAttribute(gemm2_kernel,
                         cudaFuncAttributeMaxDynamicSharedMemorySize, G2_SMEM);

    {   // convert: hs (1M x 8 floats) + W (32K x 8 floats)
        int n8_hs = 8192 * 1024 / 8;
        int n8_w  = 256 * 1024 / 8;
        int total = n8_hs + n8_w;
        split_kernel<<<(total + 255) / 256, 256>>>(hs, proj_w, n8_hs, n8_w);
    }
    {   // GEMM1: 2 x 128 tiles of 64x128
        dim3 grid(2, 128);
        gemm1_kernel<<<grid, 256, G1_SMEM>>>(proj_b);
    }
    {   // GEMM2: 136 upper-tri tiles x 4 batches
        dim3 grid(136, 1, BATCH);
        gemm2_kernel<<<grid, 256, G2_SMEM>>>(clf_w, clf_b, out);
    }
}